// round 1
// baseline (speedup 1.0000x reference)
#include <cuda_runtime.h>
#include <cuda_bf16.h>
#include <math.h>

// Problem constants (fixed shapes from reference)
#define NMAX 100000
#define EMAX 1600000
#define FIN 128
#define HD 64
#define HEADS 8
#define C1 8
#define NGRAPH 64
#define NEG_SLOPE 0.2f

// ---------------- device scratch ----------------
__device__ float g_h1[NMAX * HD];        // conv1 projected features (then reused for relu output)
__device__ float g_out1[NMAX * HD];      // conv1 aggregation output
__device__ float g_as1[NMAX * HEADS];
__device__ float g_ad1[NMAX * HEADS];
__device__ unsigned g_max1[NMAX * HEADS];
__device__ float g_den1[NMAX * HEADS];

__device__ float g_p2[NMAX * 2];
__device__ float g_as2[NMAX];
__device__ float g_ad2[NMAX];
__device__ unsigned g_max2[NMAX];
__device__ float g_den2[NMAX];
__device__ float g_out2[NMAX * 2];

__device__ float g_ps[NGRAPH * 2];
__device__ float g_cnt[NGRAPH];
__device__ int g_is64;

// ---------------- helpers ----------------
__device__ __forceinline__ long long load_idx(const void* p, long long i, int is64) {
    return is64 ? ((const long long*)p)[i] : (long long)((const int*)p)[i];
}

// order-preserving float->uint encoding for atomicMax
__device__ __forceinline__ unsigned fenc(float f) {
    unsigned u = __float_as_uint(f);
    return (u & 0x80000000u) ? ~u : (u | 0x80000000u);
}
__device__ __forceinline__ float fdec(unsigned u) {
    return (u & 0x80000000u) ? __uint_as_float(u & 0x7FFFFFFFu) : __uint_as_float(~u);
}

__device__ __forceinline__ float lrelu(float v) {
    return v > 0.f ? v : NEG_SLOPE * v;
}

// ---------------- kernels ----------------

// Detect whether index buffers are int64 (high words all zero) or int32.
__global__ void k_detect(const int* ei32) {
    int nonzero = 0;
    for (int i = 0; i < 1024; i++) {
        if (ei32[2 * i + 1] != 0) { nonzero = 1; break; }
    }
    g_is64 = nonzero ? 0 : 1;
}

__global__ void k_init(int N) {
    int i = blockIdx.x * blockDim.x + threadIdx.x;
    if (i < N * HD) g_out1[i] = 0.f;
    if (i < N * HEADS) { g_max1[i] = 0u; g_den1[i] = 0.f; }
    if (i < N * 2) g_out2[i] = 0.f;
    if (i < N) { g_max2[i] = 0u; g_den2[i] = 0.f; }
    if (i < NGRAPH * 2) g_ps[i] = 0.f;
    if (i < NGRAPH) g_cnt[i] = 0.f;
}

// h1 = x @ W1 ; per-head attention dots. One block (64 threads) per node.
__global__ void k_gemm1(const float* __restrict__ x, const float* __restrict__ W1,
                        const float* __restrict__ asw, const float* __restrict__ adw, int N) {
    __shared__ float xs[FIN];
    __shared__ float hv[HD];
    int n = blockIdx.x;
    int j = threadIdx.x;  // 0..63
    xs[j] = x[(long long)n * FIN + j];
    xs[j + 64] = x[(long long)n * FIN + 64 + j];
    __syncthreads();
    float acc = 0.f;
#pragma unroll
    for (int k = 0; k < FIN; k++) acc = fmaf(xs[k], W1[k * HD + j], acc);
    g_h1[(long long)n * HD + j] = acc;

    hv[j] = acc * asw[j];
    __syncthreads();
    if ((j & 7) == 0) {
        float s = 0.f;
#pragma unroll
        for (int c = 0; c < 8; c++) s += hv[j + c];
        g_as1[n * HEADS + (j >> 3)] = s;
    }
    __syncthreads();
    hv[j] = acc * adw[j];
    __syncthreads();
    if ((j & 7) == 0) {
        float s = 0.f;
#pragma unroll
        for (int c = 0; c < 8; c++) s += hv[j + c];
        g_ad1[n * HEADS + (j >> 3)] = s;
    }
}

// conv1 pass A: per-dst per-head max of leaky_relu attention logits
__global__ void k_edge_max1(const void* ei, int E, int N) {
    int e = blockIdx.x * blockDim.x + threadIdx.x;
    int ET = E + N;
    if (e >= ET) return;
    int is64 = g_is64;
    int s, d;
    if (e < E) {
        s = (int)load_idx(ei, e, is64);
        d = (int)load_idx(ei, (long long)E + e, is64);
    } else { s = d = e - E; }
#pragma unroll
    for (int h = 0; h < HEADS; h++) {
        float v = lrelu(g_as1[s * HEADS + h] + g_ad1[d * HEADS + h]);
        atomicMax(&g_max1[d * HEADS + h], fenc(v));
    }
}

// conv1 pass B: denom = sum exp(e - max)
__global__ void k_edge_sum1(const void* ei, int E, int N) {
    int e = blockIdx.x * blockDim.x + threadIdx.x;
    int ET = E + N;
    if (e >= ET) return;
    int is64 = g_is64;
    int s, d;
    if (e < E) {
        s = (int)load_idx(ei, e, is64);
        d = (int)load_idx(ei, (long long)E + e, is64);
    } else { s = d = e - E; }
#pragma unroll
    for (int h = 0; h < HEADS; h++) {
        float v = lrelu(g_as1[s * HEADS + h] + g_ad1[d * HEADS + h]);
        float m = fdec(g_max1[d * HEADS + h]);
        atomicAdd(&g_den1[d * HEADS + h], __expf(v - m));
    }
}

// conv1 pass C: out[dst] += alpha * h1[src]; one thread per (edge, head)
__global__ void k_edge_scat1(const void* ei, int E, int N) {
    int t = blockIdx.x * blockDim.x + threadIdx.x;
    int ET8 = (E + N) * HEADS;
    if (t >= ET8) return;
    int e = t >> 3, h = t & 7;
    int is64 = g_is64;
    int s, d;
    if (e < E) {
        s = (int)load_idx(ei, e, is64);
        d = (int)load_idx(ei, (long long)E + e, is64);
    } else { s = d = e - E; }
    float v = lrelu(g_as1[s * HEADS + h] + g_ad1[d * HEADS + h]);
    float m = fdec(g_max1[d * HEADS + h]);
    float alpha = __expf(v - m) / (g_den1[d * HEADS + h] + 1e-16f);
    const float4* hs = (const float4*)&g_h1[(long long)s * HD + h * C1];
    float4 a = hs[0];
    float4 b = hs[1];
    float* o = &g_out1[(long long)d * HD + h * C1];
    atomicAdd(o + 0, a.x * alpha);
    atomicAdd(o + 1, a.y * alpha);
    atomicAdd(o + 2, a.z * alpha);
    atomicAdd(o + 3, a.w * alpha);
    atomicAdd(o + 4, b.x * alpha);
    atomicAdd(o + 5, b.y * alpha);
    atomicAdd(o + 6, b.z * alpha);
    atomicAdd(o + 7, b.w * alpha);
}

// relu(out1 + b1) -> reuse g_h1
__global__ void k_relu_b1(const float* __restrict__ b1, int N) {
    int i = blockIdx.x * blockDim.x + threadIdx.x;
    if (i < N * HD) g_h1[i] = fmaxf(g_out1[i] + b1[i & 63], 0.f);
}

// p2 = h @ W2 ; conv2 attention scalars
__global__ void k_gemm2(const float* __restrict__ W2, const float* __restrict__ asw,
                        const float* __restrict__ adw, int N) {
    int n = blockIdx.x * blockDim.x + threadIdx.x;
    if (n >= N) return;
    float p0 = 0.f, p1 = 0.f;
    const float* hr = &g_h1[(long long)n * HD];
#pragma unroll
    for (int k = 0; k < HD; k++) {
        float hv = hr[k];
        p0 = fmaf(hv, W2[2 * k + 0], p0);
        p1 = fmaf(hv, W2[2 * k + 1], p1);
    }
    g_p2[n * 2 + 0] = p0;
    g_p2[n * 2 + 1] = p1;
    g_as2[n] = p0 * asw[0] + p1 * asw[1];
    g_ad2[n] = p0 * adw[0] + p1 * adw[1];
}

__global__ void k_edge_max2(const void* ei, int E, int N) {
    int e = blockIdx.x * blockDim.x + threadIdx.x;
    int ET = E + N;
    if (e >= ET) return;
    int is64 = g_is64;
    int s, d;
    if (e < E) {
        s = (int)load_idx(ei, e, is64);
        d = (int)load_idx(ei, (long long)E + e, is64);
    } else { s = d = e - E; }
    float v = lrelu(g_as2[s] + g_ad2[d]);
    atomicMax(&g_max2[d], fenc(v));
}

__global__ void k_edge_sum2(const void* ei, int E, int N) {
    int e = blockIdx.x * blockDim.x + threadIdx.x;
    int ET = E + N;
    if (e >= ET) return;
    int is64 = g_is64;
    int s, d;
    if (e < E) {
        s = (int)load_idx(ei, e, is64);
        d = (int)load_idx(ei, (long long)E + e, is64);
    } else { s = d = e - E; }
    float v = lrelu(g_as2[s] + g_ad2[d]);
    atomicAdd(&g_den2[d], __expf(v - fdec(g_max2[d])));
}

__global__ void k_edge_scat2(const void* ei, int E, int N) {
    int e = blockIdx.x * blockDim.x + threadIdx.x;
    int ET = E + N;
    if (e >= ET) return;
    int is64 = g_is64;
    int s, d;
    if (e < E) {
        s = (int)load_idx(ei, e, is64);
        d = (int)load_idx(ei, (long long)E + e, is64);
    } else { s = d = e - E; }
    float v = lrelu(g_as2[s] + g_ad2[d]);
    float alpha = __expf(v - fdec(g_max2[d])) / (g_den2[d] + 1e-16f);
    atomicAdd(&g_out2[d * 2 + 0], g_p2[s * 2 + 0] * alpha);
    atomicAdd(&g_out2[d * 2 + 1], g_p2[s * 2 + 1] * alpha);
}

// pooled sums via shared-memory staging (batch is sorted -> low global contention)
__global__ void k_pool(const void* bp, const float* __restrict__ b2, int N) {
    __shared__ float ss[NGRAPH * 2];
    __shared__ float sc[NGRAPH];
    int t = threadIdx.x;
    if (t < NGRAPH) { ss[2 * t] = 0.f; ss[2 * t + 1] = 0.f; sc[t] = 0.f; }
    __syncthreads();
    int n = blockIdx.x * blockDim.x + t;
    if (n < N) {
        int g = (int)load_idx(bp, n, g_is64);
        atomicAdd(&ss[g * 2 + 0], g_out2[n * 2 + 0] + b2[0]);
        atomicAdd(&ss[g * 2 + 1], g_out2[n * 2 + 1] + b2[1]);
        atomicAdd(&sc[g], 1.f);
    }
    __syncthreads();
    if (t < NGRAPH && sc[t] != 0.f) {
        atomicAdd(&g_ps[2 * t + 0], ss[2 * t + 0]);
        atomicAdd(&g_ps[2 * t + 1], ss[2 * t + 1]);
        atomicAdd(&g_cnt[t], sc[t]);
    }
}

__global__ void k_final(float* __restrict__ out) {
    int g = threadIdx.x;
    if (g >= NGRAPH) return;
    float c = fmaxf(g_cnt[g], 1.f);
    float s0 = g_ps[2 * g + 0] / c;
    float s1 = g_ps[2 * g + 1] / c;
    float m = fmaxf(s0, s1);
    float lse = m + logf(expf(s0 - m) + expf(s1 - m));
    out[2 * g + 0] = s0 - lse;
    out[2 * g + 1] = s1 - lse;
}

// ---------------- launch ----------------
extern "C" void kernel_launch(void* const* d_in, const int* in_sizes, int n_in,
                              void* d_out, int out_size) {
    const float* x = (const float*)d_in[0];
    const void* ei = d_in[1];
    const void* batch = d_in[2];
    const float* W1 = (const float*)d_in[3];
    const float* as1w = (const float*)d_in[4];
    const float* ad1w = (const float*)d_in[5];
    const float* b1 = (const float*)d_in[6];
    const float* W2 = (const float*)d_in[7];
    const float* as2w = (const float*)d_in[8];
    const float* ad2w = (const float*)d_in[9];
    const float* b2 = (const float*)d_in[10];

    int N = in_sizes[0] / FIN;
    int E = in_sizes[1] / 2;
    int ET = E + N;

    k_detect<<<1, 1>>>((const int*)ei);
    k_init<<<(N * HD + 255) / 256, 256>>>(N);
    k_gemm1<<<N, 64>>>(x, W1, as1w, ad1w, N);
    k_edge_max1<<<(ET + 255) / 256, 256>>>(ei, E, N);
    k_edge_sum1<<<(ET + 255) / 256, 256>>>(ei, E, N);
    k_edge_scat1<<<(ET * HEADS + 255) / 256, 256>>>(ei, E, N);
    k_relu_b1<<<(N * HD + 255) / 256, 256>>>(b1, N);
    k_gemm2<<<(N + 127) / 128, 128>>>(W2, as2w, ad2w, N);
    k_edge_max2<<<(ET + 255) / 256, 256>>>(ei, E, N);
    k_edge_sum2<<<(ET + 255) / 256, 256>>>(ei, E, N);
    k_edge_scat2<<<(ET + 255) / 256, 256>>>(ei, E, N);
    k_pool<<<(N + 255) / 256, 256>>>(batch, b2, N);
    k_final<<<1, 64>>>((float*)d_out);
}

// round 4
// speedup vs baseline: 2.6187x; 2.6187x over previous
#include <cuda_runtime.h>
#include <cuda_bf16.h>
#include <math.h>

#define NMAX 100000
#define EMAX 1600000
#define ETMAX (EMAX + NMAX)
#define FIN 128
#define HD 64
#define HEADS 8
#define NGRAPH 64
#define NEG_SLOPE 0.2f
#define SCAN_BLK 1024
#define MAXCHUNK ((NMAX + SCAN_BLK - 1) / SCAN_BLK)

// ---------------- device scratch ----------------
__device__ float g_h1[NMAX * HD];     // conv1 projection
__device__ float g_h2[NMAX * HD];     // conv1 output after bias+relu
__device__ float g_as1[NMAX * HEADS];
__device__ float g_ad1[NMAX * HEADS];
__device__ float g_p2[NMAX * 2];
__device__ float g_as2[NMAX];
__device__ float g_ad2[NMAX];
__device__ int g_csr[ETMAX];          // src per edge, grouped by dst
__device__ int g_rowptr[NMAX + 1];
__device__ int g_deg[NMAX];
__device__ int g_cur[NMAX];
__device__ int g_bsum[MAXCHUNK];
__device__ int g_boff[MAXCHUNK];
__device__ float g_ps[NGRAPH * 2];
__device__ int g_cnt[NGRAPH];
__device__ int g_is64;

// ---------------- helpers ----------------
__device__ __forceinline__ long long load_idx(const void* p, long long i, int is64) {
    return is64 ? ((const long long*)p)[i] : (long long)((const int*)p)[i];
}
__device__ __forceinline__ float lrelu(float v) {
    return v > 0.f ? v : NEG_SLOPE * v;
}

// ---------------- kernels ----------------
__global__ void k_detect(const int* ei32) {
    int nonzero = 0;
    for (int i = 0; i < 1024; i++) {
        if (ei32[2 * i + 1] != 0) { nonzero = 1; break; }
    }
    g_is64 = nonzero ? 0 : 1;
}

__global__ void k_init(int N) {
    int i = blockIdx.x * blockDim.x + threadIdx.x;
    if (i < N) { g_deg[i] = 0; g_cur[i] = 0; }
    if (i < NGRAPH * 2) g_ps[i] = 0.f;
    if (i < NGRAPH) g_cnt[i] = 0;
}

// histogram of dst degrees (edges + self loops)
__global__ void k_hist(const void* ei, int E, int N) {
    int e = blockIdx.x * blockDim.x + threadIdx.x;
    if (e >= E + N) return;
    int d;
    if (e < E) d = (int)load_idx(ei, (long long)E + e, g_is64);
    else d = e - E;
    atomicAdd(&g_deg[d], 1);
}

// 3-kernel exclusive scan over g_deg -> g_rowptr
__global__ void k_scan1(int N) {
    __shared__ int sh[SCAN_BLK];
    int i = blockIdx.x * SCAN_BLK + threadIdx.x;
    int v = (i < N) ? g_deg[i] : 0;
    sh[threadIdx.x] = v;
    __syncthreads();
    int val = v;
    for (int o = 1; o < SCAN_BLK; o <<= 1) {
        int t = (threadIdx.x >= o) ? sh[threadIdx.x - o] : 0;
        __syncthreads();
        val += t;
        sh[threadIdx.x] = val;
        __syncthreads();
    }
    if (i < N) g_rowptr[i] = val - v;  // chunk-local exclusive
    if (threadIdx.x == SCAN_BLK - 1) g_bsum[blockIdx.x] = val;
}
__global__ void k_scan2(int nchunk, int N) {
    if (threadIdx.x == 0) {
        int run = 0;
        for (int c = 0; c < nchunk; c++) { g_boff[c] = run; run += g_bsum[c]; }
        g_rowptr[N] = run;
    }
}
__global__ void k_scan3(int N) {
    int i = blockIdx.x * blockDim.x + threadIdx.x;
    if (i < N) g_rowptr[i] += g_boff[i / SCAN_BLK];
}

// scatter edges into CSR slots
__global__ void k_scatter(const void* ei, int E, int N) {
    int e = blockIdx.x * blockDim.x + threadIdx.x;
    if (e >= E + N) return;
    int s, d;
    if (e < E) {
        s = (int)load_idx(ei, e, g_is64);
        d = (int)load_idx(ei, (long long)E + e, g_is64);
    } else { s = d = e - E; }
    int pos = atomicAdd(&g_cur[d], 1);
    g_csr[g_rowptr[d] + pos] = s;
}

// h1 = x @ W1 : 64 nodes x 64 ch per block, 4x4 per thread
__global__ __launch_bounds__(256) void k_gemm1(const float* __restrict__ x,
                                               const float* __restrict__ W1, int N) {
    __shared__ float xs[16][68];  // [kk][node], pad 68 (mult of 4, bank-spread)
    __shared__ float ws[16][64];  // [kk][ch]
    int tid = threadIdx.x;
    int tx = tid & 15;   // ch group (4 ch)
    int ty = tid >> 4;   // node group (4 nodes)
    int n0 = blockIdx.x * 64;
    float acc[4][4] = {};
    for (int k0 = 0; k0 < FIN; k0 += 16) {
#pragma unroll
        for (int r = 0; r < 4; r++) {
            int id = tid + 256 * r;
            int node = id >> 4, kk = id & 15;
            int gn = n0 + node;
            xs[kk][node] = (gn < N) ? x[(size_t)gn * FIN + k0 + kk] : 0.f;
        }
#pragma unroll
        for (int r = 0; r < 4; r++) {
            int id = tid + 256 * r;
            int kk = id >> 6, ch = id & 63;
            ws[kk][ch] = W1[(k0 + kk) * HD + ch];
        }
        __syncthreads();
#pragma unroll
        for (int kk = 0; kk < 16; kk++) {
            float4 xv = *(float4*)&xs[kk][ty * 4];
            float4 wv = *(float4*)&ws[kk][tx * 4];
            float xa[4] = {xv.x, xv.y, xv.z, xv.w};
            float wa[4] = {wv.x, wv.y, wv.z, wv.w};
#pragma unroll
            for (int i = 0; i < 4; i++)
#pragma unroll
                for (int j = 0; j < 4; j++)
                    acc[i][j] = fmaf(xa[i], wa[j], acc[i][j]);
        }
        __syncthreads();
    }
#pragma unroll
    for (int i = 0; i < 4; i++) {
        int gn = n0 + ty * 4 + i;
        if (gn < N) {
            float4 v = make_float4(acc[i][0], acc[i][1], acc[i][2], acc[i][3]);
            *(float4*)&g_h1[(size_t)gn * HD + tx * 4] = v;
        }
    }
}

// attention dots per (node, head)
__global__ void k_att1(const float* __restrict__ asw, const float* __restrict__ adw, int N) {
    int t = blockIdx.x * blockDim.x + threadIdx.x;
    if (t >= N * HEADS) return;
    int n = t >> 3, h = t & 7;
    const float4* hp = (const float4*)&g_h1[(size_t)n * HD + h * 8];
    float4 a = hp[0], b = hp[1];
    const float* s = &asw[h * 8];
    const float* d = &adw[h * 8];
    g_as1[t] = a.x * s[0] + a.y * s[1] + a.z * s[2] + a.w * s[3]
             + b.x * s[4] + b.y * s[5] + b.z * s[6] + b.w * s[7];
    g_ad1[t] = a.x * d[0] + a.y * d[1] + a.z * d[2] + a.w * d[3]
             + b.x * d[4] + b.y * d[5] + b.z * d[6] + b.w * d[7];
}

// conv1 gather: warp per dst, lane handles 2 channels; fused softmax-normalize + bias + relu
__global__ __launch_bounds__(128) void k_gather1(const float* __restrict__ b1, int N) {
    int w = (blockIdx.x * 128 + threadIdx.x) >> 5;
    int lane = threadIdx.x & 31;
    if (w >= N) return;
    int d = w;
    int beg = g_rowptr[d];
    int end = beg + g_deg[d];
    int hidx = lane >> 2;  // head of channels 2*lane, 2*lane+1
    float ad = g_ad1[d * HEADS + hidx];
    float a0 = 0.f, a1 = 0.f, den = 0.f;
    int i = beg;
    int s = g_csr[i];
    while (i < end) {
        int i2 = i + 1;
        int s_next = (i2 < end) ? g_csr[i2] : 0;
        float as = g_as1[s * HEADS + hidx];
        float ex = __expf(lrelu(as + ad));
        float2 hv = *(const float2*)&g_h1[(size_t)s * HD + lane * 2];
        den += ex;
        a0 = fmaf(ex, hv.x, a0);
        a1 = fmaf(ex, hv.y, a1);
        s = s_next;
        i = i2;
    }
    float inv = 1.f / (den + 1e-16f);
    int ch = lane * 2;
    g_h2[(size_t)d * HD + ch]     = fmaxf(a0 * inv + b1[ch], 0.f);
    g_h2[(size_t)d * HD + ch + 1] = fmaxf(a1 * inv + b1[ch + 1], 0.f);
}

// p2 = h2 @ W2 (warp per node), plus conv2 attention scalars
__global__ void k_gemm2(const float* __restrict__ W2, const float* __restrict__ asw,
                        const float* __restrict__ adw, int N) {
    int w = (blockIdx.x * blockDim.x + threadIdx.x) >> 5;
    int lane = threadIdx.x & 31;
    if (w >= N) return;
    float h0 = g_h2[(size_t)w * HD + lane];
    float h1 = g_h2[(size_t)w * HD + 32 + lane];
    float p0 = h0 * W2[2 * lane]     + h1 * W2[2 * (lane + 32)];
    float p1 = h0 * W2[2 * lane + 1] + h1 * W2[2 * (lane + 32) + 1];
#pragma unroll
    for (int o = 16; o; o >>= 1) {
        p0 += __shfl_xor_sync(0xFFFFFFFFu, p0, o);
        p1 += __shfl_xor_sync(0xFFFFFFFFu, p1, o);
    }
    if (lane == 0) {
        g_p2[2 * w]     = p0;
        g_p2[2 * w + 1] = p1;
        g_as2[w] = p0 * asw[0] + p1 * asw[1];
        g_ad2[w] = p0 * adw[0] + p1 * adw[1];
    }
}

// conv2 gather (warp per dst, lanes stride edges) fused with graph pooling
__global__ __launch_bounds__(128) void k_gather2(const void* bp, int N) {
    int w = (blockIdx.x * 128 + threadIdx.x) >> 5;
    int lane = threadIdx.x & 31;
    if (w >= N) return;
    int d = w;
    int beg = g_rowptr[d];
    int end = beg + g_deg[d];
    float ad = g_ad2[d];
    float den = 0.f, a0 = 0.f, a1 = 0.f;
    for (int i = beg + lane; i < end; i += 32) {
        int s = g_csr[i];
        float ex = __expf(lrelu(g_as2[s] + ad));
        float2 p = *(const float2*)&g_p2[2 * s];
        den += ex;
        a0 = fmaf(ex, p.x, a0);
        a1 = fmaf(ex, p.y, a1);
    }
#pragma unroll
    for (int o = 16; o; o >>= 1) {
        den += __shfl_xor_sync(0xFFFFFFFFu, den, o);
        a0  += __shfl_xor_sync(0xFFFFFFFFu, a0, o);
        a1  += __shfl_xor_sync(0xFFFFFFFFu, a1, o);
    }
    if (lane == 0) {
        float inv = 1.f / (den + 1e-16f);
        int g = (int)load_idx(bp, d, g_is64);
        atomicAdd(&g_ps[2 * g],     a0 * inv);
        atomicAdd(&g_ps[2 * g + 1], a1 * inv);
        atomicAdd(&g_cnt[g], 1);
    }
}

__global__ void k_final(const float* __restrict__ b2, float* __restrict__ out) {
    int g = threadIdx.x;
    if (g >= NGRAPH) return;
    float c = fmaxf((float)g_cnt[g], 1.f);
    float s0 = g_ps[2 * g]     / c + b2[0];
    float s1 = g_ps[2 * g + 1] / c + b2[1];
    float m = fmaxf(s0, s1);
    float lse = m + logf(expf(s0 - m) + expf(s1 - m));
    out[2 * g]     = s0 - lse;
    out[2 * g + 1] = s1 - lse;
}

// ---------------- launch ----------------
extern "C" void kernel_launch(void* const* d_in, const int* in_sizes, int n_in,
                              void* d_out, int out_size) {
    const float* x = (const float*)d_in[0];
    const void* ei = d_in[1];
    const void* batch = d_in[2];
    const float* W1 = (const float*)d_in[3];
    const float* as1w = (const float*)d_in[4];
    const float* ad1w = (const float*)d_in[5];
    const float* b1 = (const float*)d_in[6];
    const float* W2 = (const float*)d_in[7];
    const float* as2w = (const float*)d_in[8];
    const float* ad2w = (const float*)d_in[9];
    const float* b2 = (const float*)d_in[10];

    int N = in_sizes[0] / FIN;
    int E = in_sizes[1] / 2;
    int ET = E + N;
    int nchunk = (N + SCAN_BLK - 1) / SCAN_BLK;

    k_detect<<<1, 1>>>((const int*)ei);
    k_init<<<(N + 255) / 256, 256>>>(N);
    k_hist<<<(ET + 255) / 256, 256>>>(ei, E, N);
    k_scan1<<<nchunk, SCAN_BLK>>>(N);
    k_scan2<<<1, 32>>>(nchunk, N);
    k_scan3<<<(N + 255) / 256, 256>>>(N);
    k_scatter<<<(ET + 255) / 256, 256>>>(ei, E, N);
    k_gemm1<<<(N + 63) / 64, 256>>>(x, W1, N);
    k_att1<<<(N * HEADS + 255) / 256, 256>>>(as1w, ad1w, N);
    k_gather1<<<(N + 3) / 4, 128>>>(b1, N);
    k_gemm2<<<(N * 32 + 255) / 256, 256>>>(W2, as2w, ad2w, N);
    k_gather2<<<(N + 3) / 4, 128>>>(batch, N);
    k_final<<<1, 64>>>(b2, (float*)d_out);
}

// round 5
// speedup vs baseline: 2.8508x; 1.0886x over previous
#include <cuda_runtime.h>
#include <cuda_bf16.h>
#include <math.h>

#define NMAX 100000
#define EMAX 1600000
#define ETMAX (EMAX + NMAX)
#define FIN 128
#define HD 64
#define HEADS 8
#define NGRAPH 64
#define NEG_SLOPE 0.2f
#define SCAN_BLK 1024
#define MAXCHUNK ((NMAX + SCAN_BLK - 1) / SCAN_BLK)

// ---------------- device scratch ----------------
__device__ float g_h1[NMAX * HD];     // conv1 projection
__device__ float g_h2[NMAX * HD];     // conv1 output after bias+relu
__device__ float g_as1[NMAX * HEADS];
__device__ float g_ad1[NMAX * HEADS];
__device__ float g_p2[NMAX * 2];
__device__ float g_as2[NMAX];
__device__ float g_ad2[NMAX];
__device__ int g_csr[ETMAX];          // src per edge, grouped by dst
__device__ int g_rowptr[NMAX + 1];
__device__ int g_deg[NMAX];
__device__ int g_cur[NMAX];
__device__ int g_bsum[MAXCHUNK];
__device__ int g_boff[MAXCHUNK];
__device__ float g_ps[NGRAPH * 2];
__device__ int g_cnt[NGRAPH];
__device__ int g_is64;

// ---------------- helpers ----------------
__device__ __forceinline__ long long load_idx(const void* p, long long i, int is64) {
    return is64 ? ((const long long*)p)[i] : (long long)((const int*)p)[i];
}
__device__ __forceinline__ float lrelu(float v) {
    return v > 0.f ? v : NEG_SLOPE * v;
}

// ---------------- kernels ----------------
// Parallel int64-vs-int32 detection: if indices are int64, every odd 32-bit
// slot (high word) is zero. 256 threads scan 1024 slots.
__global__ void k_detect(const int* ei32) {
    int t = threadIdx.x;
    int nz = 0;
    for (int i = t; i < 1024; i += 256) nz |= ei32[2 * i + 1];
    nz = __syncthreads_or(nz);
    if (t == 0) g_is64 = nz ? 0 : 1;
}

__global__ void k_init(int N) {
    int i = blockIdx.x * blockDim.x + threadIdx.x;
    if (i < N) g_deg[i] = 0;
    if (i < NGRAPH * 2) g_ps[i] = 0.f;
    if (i < NGRAPH) g_cnt[i] = 0;
}

// histogram of dst degrees (edges + self loops)
__global__ void k_hist(const void* ei, int E, int N) {
    int e = blockIdx.x * blockDim.x + threadIdx.x;
    if (e >= E + N) return;
    int d;
    if (e < E) d = (int)load_idx(ei, (long long)E + e, g_is64);
    else d = e - E;
    atomicAdd(&g_deg[d], 1);
}

// 3-kernel exclusive scan over g_deg -> g_rowptr (g_cur gets a copy for scatter)
__global__ void k_scan1(int N) {
    __shared__ int sh[SCAN_BLK];
    int i = blockIdx.x * SCAN_BLK + threadIdx.x;
    int v = (i < N) ? g_deg[i] : 0;
    sh[threadIdx.x] = v;
    __syncthreads();
    int val = v;
    for (int o = 1; o < SCAN_BLK; o <<= 1) {
        int t = (threadIdx.x >= o) ? sh[threadIdx.x - o] : 0;
        __syncthreads();
        val += t;
        sh[threadIdx.x] = val;
        __syncthreads();
    }
    if (i < N) g_rowptr[i] = val - v;  // chunk-local exclusive
    if (threadIdx.x == SCAN_BLK - 1) g_bsum[blockIdx.x] = val;
}
__global__ void k_scan2(int nchunk, int N) {
    __shared__ int sh[128];
    int t = threadIdx.x;
    int v = (t < nchunk) ? g_bsum[t] : 0;
    sh[t] = v;
    __syncthreads();
    int val = v;
    for (int o = 1; o < 128; o <<= 1) {
        int u = (t >= o) ? sh[t - o] : 0;
        __syncthreads();
        val += u;
        sh[t] = val;
        __syncthreads();
    }
    if (t < nchunk) g_boff[t] = val - v;  // exclusive
    if (t == nchunk - 1) g_rowptr[N] = val;
}
__global__ void k_scan3(int N) {
    int i = blockIdx.x * blockDim.x + threadIdx.x;
    if (i < N) {
        int r = g_rowptr[i] + g_boff[i / SCAN_BLK];
        g_rowptr[i] = r;
        g_cur[i] = r;  // scatter cursor starts at row base
    }
}

// scatter edges into CSR slots
__global__ void k_scatter(const void* ei, int E, int N) {
    int e = blockIdx.x * blockDim.x + threadIdx.x;
    if (e >= E + N) return;
    int s, d;
    if (e < E) {
        s = (int)load_idx(ei, e, g_is64);
        d = (int)load_idx(ei, (long long)E + e, g_is64);
    } else { s = d = e - E; }
    int pos = atomicAdd(&g_cur[d], 1);
    g_csr[pos] = s;
}

// h1 = x @ W1 : 64 nodes x 64 ch per block, 4x4 per thread.
// Fused epilogue computes per-(node,head) attention dots via lane-pair shfl.
__global__ __launch_bounds__(256) void k_gemm1(const float* __restrict__ x,
                                               const float* __restrict__ W1,
                                               const float* __restrict__ asw,
                                               const float* __restrict__ adw, int N) {
    __shared__ float xs[16][68];  // [kk][node]
    __shared__ float ws[16][64];  // [kk][ch]
    int tid = threadIdx.x;
    int tx = tid & 15;   // ch group (4 ch)
    int ty = tid >> 4;   // node group (4 nodes)
    int n0 = blockIdx.x * 64;
    float acc[4][4] = {};
    for (int k0 = 0; k0 < FIN; k0 += 16) {
#pragma unroll
        for (int r = 0; r < 4; r++) {
            int id = tid + 256 * r;
            int node = id >> 4, kk = id & 15;
            int gn = n0 + node;
            xs[kk][node] = (gn < N) ? x[(size_t)gn * FIN + k0 + kk] : 0.f;
        }
#pragma unroll
        for (int r = 0; r < 4; r++) {
            int id = tid + 256 * r;
            int kk = id >> 6, ch = id & 63;
            ws[kk][ch] = W1[(k0 + kk) * HD + ch];
        }
        __syncthreads();
#pragma unroll
        for (int kk = 0; kk < 16; kk++) {
            float4 xv = *(float4*)&xs[kk][ty * 4];
            float4 wv = *(float4*)&ws[kk][tx * 4];
            float xa[4] = {xv.x, xv.y, xv.z, xv.w};
            float wa[4] = {wv.x, wv.y, wv.z, wv.w};
#pragma unroll
            for (int i = 0; i < 4; i++)
#pragma unroll
                for (int j = 0; j < 4; j++)
                    acc[i][j] = fmaf(xa[i], wa[j], acc[i][j]);
        }
        __syncthreads();
    }
    // attention weight slices for this thread's 4 channels
    float aswv[4], adwv[4];
#pragma unroll
    for (int j = 0; j < 4; j++) {
        aswv[j] = asw[tx * 4 + j];
        adwv[j] = adw[tx * 4 + j];
    }
    int hidx = tx >> 1;  // head covered by lane pair (tx, tx^1)
#pragma unroll
    for (int i = 0; i < 4; i++) {
        int gn = n0 + ty * 4 + i;
        float ps = 0.f, pd = 0.f;
#pragma unroll
        for (int j = 0; j < 4; j++) {
            ps = fmaf(acc[i][j], aswv[j], ps);
            pd = fmaf(acc[i][j], adwv[j], pd);
        }
        ps += __shfl_xor_sync(0xFFFFFFFFu, ps, 1);
        pd += __shfl_xor_sync(0xFFFFFFFFu, pd, 1);
        if (gn < N) {
            float4 v = make_float4(acc[i][0], acc[i][1], acc[i][2], acc[i][3]);
            *(float4*)&g_h1[(size_t)gn * HD + tx * 4] = v;
            if ((tx & 1) == 0) {
                g_as1[gn * HEADS + hidx] = ps;
                g_ad1[gn * HEADS + hidx] = pd;
            }
        }
    }
}

// conv1 gather: warp per dst, lane handles 2 channels; 2-edge unroll for MLP.
// Fused softmax-normalize + bias + relu.
__global__ __launch_bounds__(128) void k_gather1(const float* __restrict__ b1, int N) {
    int w = (blockIdx.x * 128 + threadIdx.x) >> 5;
    int lane = threadIdx.x & 31;
    if (w >= N) return;
    int d = w;
    int beg = g_rowptr[d];
    int end = g_rowptr[d + 1];
    int hidx = lane >> 2;
    float ad = g_ad1[d * HEADS + hidx];
    float a0 = 0.f, a1 = 0.f, den = 0.f;
    int i = beg;
    for (; i + 1 < end; i += 2) {
        int s0 = g_csr[i];
        int s1 = g_csr[i + 1];
        float as0 = g_as1[s0 * HEADS + hidx];
        float as1 = g_as1[s1 * HEADS + hidx];
        float2 hv0 = *(const float2*)&g_h1[(size_t)s0 * HD + lane * 2];
        float2 hv1 = *(const float2*)&g_h1[(size_t)s1 * HD + lane * 2];
        float ex0 = __expf(lrelu(as0 + ad));
        float ex1 = __expf(lrelu(as1 + ad));
        den += ex0 + ex1;
        a0 = fmaf(ex0, hv0.x, a0);
        a1 = fmaf(ex0, hv0.y, a1);
        a0 = fmaf(ex1, hv1.x, a0);
        a1 = fmaf(ex1, hv1.y, a1);
    }
    if (i < end) {
        int s = g_csr[i];
        float as = g_as1[s * HEADS + hidx];
        float ex = __expf(lrelu(as + ad));
        float2 hv = *(const float2*)&g_h1[(size_t)s * HD + lane * 2];
        den += ex;
        a0 = fmaf(ex, hv.x, a0);
        a1 = fmaf(ex, hv.y, a1);
    }
    float inv = 1.f / (den + 1e-16f);
    int ch = lane * 2;
    g_h2[(size_t)d * HD + ch]     = fmaxf(a0 * inv + b1[ch], 0.f);
    g_h2[(size_t)d * HD + ch + 1] = fmaxf(a1 * inv + b1[ch + 1], 0.f);
}

// p2 = h2 @ W2 (warp per node), plus conv2 attention scalars
__global__ void k_gemm2(const float* __restrict__ W2, const float* __restrict__ asw,
                        const float* __restrict__ adw, int N) {
    int w = (blockIdx.x * blockDim.x + threadIdx.x) >> 5;
    int lane = threadIdx.x & 31;
    if (w >= N) return;
    float h0 = g_h2[(size_t)w * HD + lane];
    float h1 = g_h2[(size_t)w * HD + 32 + lane];
    float p0 = h0 * W2[2 * lane]     + h1 * W2[2 * (lane + 32)];
    float p1 = h0 * W2[2 * lane + 1] + h1 * W2[2 * (lane + 32) + 1];
#pragma unroll
    for (int o = 16; o; o >>= 1) {
        p0 += __shfl_xor_sync(0xFFFFFFFFu, p0, o);
        p1 += __shfl_xor_sync(0xFFFFFFFFu, p1, o);
    }
    if (lane == 0) {
        g_p2[2 * w]     = p0;
        g_p2[2 * w + 1] = p1;
        g_as2[w] = p0 * asw[0] + p1 * asw[1];
        g_ad2[w] = p0 * adw[0] + p1 * adw[1];
    }
}

// conv2 gather (warp per dst, lanes stride edges) fused with graph pooling
__global__ __launch_bounds__(128) void k_gather2(const void* bp, int N) {
    int w = (blockIdx.x * 128 + threadIdx.x) >> 5;
    int lane = threadIdx.x & 31;
    if (w >= N) return;
    int d = w;
    int beg = g_rowptr[d];
    int end = g_rowptr[d + 1];
    float ad = g_ad2[d];
    float den = 0.f, a0 = 0.f, a1 = 0.f;
    for (int i = beg + lane; i < end; i += 32) {
        int s = g_csr[i];
        float ex = __expf(lrelu(g_as2[s] + ad));
        float2 p = *(const float2*)&g_p2[2 * s];
        den += ex;
        a0 = fmaf(ex, p.x, a0);
        a1 = fmaf(ex, p.y, a1);
    }
#pragma unroll
    for (int o = 16; o; o >>= 1) {
        den += __shfl_xor_sync(0xFFFFFFFFu, den, o);
        a0  += __shfl_xor_sync(0xFFFFFFFFu, a0, o);
        a1  += __shfl_xor_sync(0xFFFFFFFFu, a1, o);
    }
    if (lane == 0) {
        float inv = 1.f / (den + 1e-16f);
        int g = (int)load_idx(bp, d, g_is64);
        atomicAdd(&g_ps[2 * g],     a0 * inv);
        atomicAdd(&g_ps[2 * g + 1], a1 * inv);
        atomicAdd(&g_cnt[g], 1);
    }
}

__global__ void k_final(const float* __restrict__ b2, float* __restrict__ out) {
    int g = threadIdx.x;
    if (g >= NGRAPH) return;
    float c = fmaxf((float)g_cnt[g], 1.f);
    float s0 = g_ps[2 * g]     / c + b2[0];
    float s1 = g_ps[2 * g + 1] / c + b2[1];
    float m = fmaxf(s0, s1);
    float lse = m + logf(expf(s0 - m) + expf(s1 - m));
    out[2 * g]     = s0 - lse;
    out[2 * g + 1] = s1 - lse;
}

// ---------------- launch ----------------
extern "C" void kernel_launch(void* const* d_in, const int* in_sizes, int n_in,
                              void* d_out, int out_size) {
    const float* x = (const float*)d_in[0];
    const void* ei = d_in[1];
    const void* batch = d_in[2];
    const float* W1 = (const float*)d_in[3];
    const float* as1w = (const float*)d_in[4];
    const float* ad1w = (const float*)d_in[5];
    const float* b1 = (const float*)d_in[6];
    const float* W2 = (const float*)d_in[7];
    const float* as2w = (const float*)d_in[8];
    const float* ad2w = (const float*)d_in[9];
    const float* b2 = (const float*)d_in[10];

    int N = in_sizes[0] / FIN;
    int E = in_sizes[1] / 2;
    int ET = E + N;
    int nchunk = (N + SCAN_BLK - 1) / SCAN_BLK;

    // Fork/join resources (created per call; intentionally not destroyed —
    // destroying capture-participating streams/events during capture is illegal.
    // kernel_launch runs only for the correctness call + one capture call.)
    cudaStream_t s2;
    cudaEvent_t e1, e2;
    cudaStreamCreateWithFlags(&s2, cudaStreamNonBlocking);
    cudaEventCreateWithFlags(&e1, cudaEventDisableTiming);
    cudaEventCreateWithFlags(&e2, cudaEventDisableTiming);

    // main stream: detect, then fork
    k_detect<<<1, 256>>>((const int*)ei);
    cudaEventRecord(e1, 0);
    cudaStreamWaitEvent(s2, e1, 0);

    // branch A (s2): CSR build
    k_init<<<(N + 255) / 256, 256, 0, s2>>>(N);
    k_hist<<<(ET + 255) / 256, 256, 0, s2>>>(ei, E, N);
    k_scan1<<<nchunk, SCAN_BLK, 0, s2>>>(N);
    k_scan2<<<1, 128, 0, s2>>>(nchunk, N);
    k_scan3<<<(N + 255) / 256, 256, 0, s2>>>(N);
    k_scatter<<<(ET + 255) / 256, 256, 0, s2>>>(ei, E, N);
    cudaEventRecord(e2, s2);

    // branch B (main): projection GEMM + fused attention dots
    k_gemm1<<<(N + 63) / 64, 256>>>(x, W1, as1w, ad1w, N);

    // join, then the dependent tail
    cudaStreamWaitEvent(0, e2, 0);
    k_gather1<<<(N + 3) / 4, 128>>>(b1, N);
    k_gemm2<<<(N * 32 + 255) / 256, 256>>>(W2, as2w, ad2w, N);
    k_gather2<<<(N + 3) / 4, 128>>>(batch, N);
    k_final<<<1, 64>>>(b2, (float*)d_out);
}